// round 15
// baseline (speedup 1.0000x reference)
#include <cuda_runtime.h>
#include <math.h>

#define BATCH 256
#define S 64

__device__ float g_loss[BATCH];
__device__ unsigned int g_count;

// order-preserving float<->uint keys
__device__ __forceinline__ unsigned okey(float f) {
    unsigned u = __float_as_uint(f);
    return u ^ (((unsigned)((int)u >> 31)) | 0x80000000u);
}
__device__ __forceinline__ float dokey(unsigned k) {
    unsigned m = (((unsigned)((int)(~k) >> 31)) | 0x80000000u);
    return __uint_as_float(k ^ m);
}

// numpy pairwise-order cost, no FMA contraction
__device__ __forceinline__ float cost10(const float* a, const float* g) {
    float d0 = fabsf(a[0] - g[0]), d1 = fabsf(a[1] - g[1]);
    float d2 = fabsf(a[2] - g[2]), d3 = fabsf(a[3] - g[3]);
    float d4 = fabsf(a[4] - g[4]), d5 = fabsf(a[5] - g[5]);
    float d6 = fabsf(a[6] - g[6]), d7 = fabsf(a[7] - g[7]);
    float d8 = fabsf(a[8] - g[8]), d9 = fabsf(a[9] - g[9]);
    float s8 = __fadd_rn(__fadd_rn(__fadd_rn(d0, d1), __fadd_rn(d2, d3)),
                         __fadd_rn(__fadd_rn(d4, d5), __fadd_rn(d6, d7)));
    return __fadd_rn(__fmul_rn(5.f, s8), __fadd_rn(d8, d9));
}

__global__ void __launch_bounds__(128) detr_fused_kernel(
    const float* __restrict__ pred_strokes,   // [B,S,10]
    const float* __restrict__ pred_validity,  // [B,S,1]
    const float* __restrict__ targets,        // [B,S,11]
    float* __restrict__ out)
{
    const int b = blockIdx.x;
    const int tid = threadIdx.x;
    const int wid = tid >> 5;
    const int lane = tid & 31;
    const unsigned FULL = 0xffffffffu;
    const float INFV = __int_as_float(0x7f800000);

    __shared__ float ps[S * 10];
    __shared__ float gt[S * 10];
    __shared__ float C[S * 64];
    __shared__ float u_sh[S + 1];              // read-only after build
    __shared__ unsigned long long tight[S];
    __shared__ float bce_sh;

    const float* tgb = targets + b * (S * 11);
    const float* psb = pred_strokes + b * (S * 10);
    const float* pvb = pred_validity + b * S;

    // ---- stage 1: ps staging (all warps) + redundant per-warp compaction ----
    for (int idx = tid; idx < S * 10; idx += 128) ps[idx] = psb[idx];

    // every warp computes the compaction masks locally (registers only)
    const float gv0 = tgb[lane * 11 + 10];
    const float gv1 = tgb[(lane + 32) * 11 + 10];
    const unsigned m0 = __ballot_sync(FULL, gv0 > 0.5f);
    const unsigned m1 = __ballot_sync(FULL, gv1 > 0.5f);
    const int c0 = __popc(m0);
    const int n = c0 + __popc(m1);

    if (wid == 1) {
        // BCE over all 64 slots (warp 1 only; overlaps other warps' staging)
        float pv0 = pvb[lane], pv1 = pvb[lane + 32];
        float bce = -(gv0 * fmaxf(logf(pv0), -100.f) + (1.f - gv0) * fmaxf(logf(1.f - pv0), -100.f))
                    - (gv1 * fmaxf(logf(pv1), -100.f) + (1.f - gv1) * fmaxf(logf(1.f - pv1), -100.f));
        #pragma unroll
        for (int o = 16; o; o >>= 1) bce += __shfl_xor_sync(FULL, bce, o);
        if (lane == 0) bce_sh = bce * (1.f / 64.f);
    }

    const bool transposed = (n < 64);
    const int r0 = (wid * n) >> 2;
    const int r1 = ((wid + 1) * n) >> 2;

    // ---- stage 2: gt staging for this warp's own build range (no barrier needed:
    //      mapping comes from this warp's own ballot masks via __fns) ----
    for (int idx = r0 * 10 + lane; idx < r1 * 10; idx += 32) {
        int r = idx / 10, k = idx - r * 10;
        int slot = (r < c0) ? (int)__fns(m0, 0, r + 1)
                            : (32 + (int)__fns(m1, 0, r - c0 + 1));
        gt[idx] = tgb[slot * 11 + k];
    }
    __syncwarp();          // this warp's gt range visible to all its lanes
    __syncthreads();       // ps fully staged before build reads it

    // ---- stage 3: cost build (4-way row split) + per-row raw min + tight mask ----
    if (n > 0) {
        if (transposed) {
            float pa[10], pb[10];
            #pragma unroll
            for (int k = 0; k < 10; k++) {
                pa[k] = ps[lane * 10 + k];
                pb[k] = ps[(lane + 32) * 10 + k];
            }
            for (int i = r0; i < r1; i++) {
                float g[10];
                #pragma unroll
                for (int k = 0; k < 10; k++) g[k] = gt[i * 10 + k];  // broadcast
                float cA = cost10(pa, g);
                float cB = cost10(pb, g);
                C[i * 64 + lane] = cA;
                C[i * 64 + lane + 32] = cB;
                unsigned mk = __reduce_min_sync(FULL, min(okey(cA), okey(cB)));
                float ui = dokey(mk);
                unsigned bA = __ballot_sync(FULL, cA == ui);
                unsigned bB = __ballot_sync(FULL, cB == ui);
                if (lane == 0) {
                    u_sh[i + 1] = ui;
                    tight[i] = (unsigned long long)bA | ((unsigned long long)bB << 32);
                }
            }
        } else {
            // generic n==64 path (statistically never taken): needs all gt staged
            __syncthreads();
            for (int idx = tid; idx < 64 * 64; idx += 128) {
                int i = idx >> 6, j = idx & 63;
                C[idx] = cost10(&ps[i * 10], &gt[j * 10]);
            }
        }
    }
    __syncthreads();

    if (wid != 0) return;   // warps 1-3 done; warp 0 owns the sequential tail

    float loss;
    if (n == 0) {
        loss = bce_sh;
    } else {
        if (!transposed) {
            // generic path: row mins + tight masks (warp 0, per-row cooperative)
            for (int i = 0; i < n; i++) {
                float cA = C[i * 64 + lane];
                float cB = C[i * 64 + lane + 32];
                unsigned mk = __reduce_min_sync(FULL, min(okey(cA), okey(cB)));
                float ui = dokey(mk);
                unsigned bA = __ballot_sync(FULL, cA == ui);
                unsigned bB = __ballot_sync(FULL, cB == ui);
                if (lane == 0) {
                    u_sh[i + 1] = ui;
                    tight[i] = (unsigned long long)bA | ((unsigned long long)bB << 32);
                }
            }
            __syncwarp();
        }

        const int jA = lane + 1, jB = lane + 33;
        float vA = 0.f, vB = 0.f;
        int pA = 0, pB = 0;
        unsigned long long rowdone = 0ull;

        // ---- greedy tight-edge assignment (scalar bitmask scan, prefetched) ----
        {
            unsigned long long freecols = ~0ull;
            unsigned long long tcur = tight[0];
            for (int i = 0; i < n; i++) {
                int nxt = (i + 1 < S) ? (i + 1) : (S - 1);
                unsigned long long tnext = tight[nxt];   // prefetch next row's mask
                unsigned long long t = tcur & freecols;
                if (t) {
                    int j = __ffsll((long long)t) - 1;   // column index 0..63
                    freecols &= ~(1ull << j);
                    rowdone |= 1ull << i;
                    if (j == lane) pA = i + 1;
                    if (j == lane + 32) pB = i + 1;
                }
                tcur = tnext;
            }
        }

        // dual cache: owning lane of each assigned column caches u[p[col]]
        float uA_c = (pA > 0) ? u_sh[pA] : 0.f;
        float uB_c = (pB > 0) ? u_sh[pB] : 0.f;

        // ---- shortest augmenting path phases for remaining rows ----
        // u_sh read-only; dual updates in registers; no shared writes, no syncwarp.
        for (int i = 1; i <= n; i++) {
            if ((rowdone >> (i - 1)) & 1ull) continue;

            float distA = INFV, distB = INFV;
            int wayA = 0, wayB = 0;
            bool usedA = false, usedB = false;
            const float u_i_start = u_sh[i];   // build value: free rows never updated
            float ucur = u_i_start;
            float d0 = 0.f;
            int j0 = 0;
            const float* Crow = &C[(i - 1) * 64];

            while (true) {
                if (j0 == jA) usedA = true;
                if (j0 == jB) usedB = true;

                float base = d0 - ucur;
                if (!usedA) {
                    float cur = base + (Crow[lane] - vA);
                    if (cur < distA) { distA = cur; wayA = j0; }
                }
                if (!usedB) {
                    float cur = base + (Crow[lane + 32] - vB);
                    if (cur < distB) { distB = cur; wayB = j0; }
                }
                // packed argmin: key's 6 LSBs carry the column index
                unsigned kA = usedA ? 0xFFFFFFFFu : okey(distA);
                unsigned kB = usedB ? 0xFFFFFFFFu : okey(distB);
                unsigned pkA = (kA & 0xFFFFFFC0u) | (unsigned)lane;
                unsigned pkB = (kB & 0xFFFFFFC0u) | (unsigned)(lane + 32);
                unsigned w = __reduce_min_sync(FULL, min(pkA, pkB));
                int col = (int)(w & 63u);
                int owner = col & 31;
                bool isB = col >= 32;
                d0 = __shfl_sync(FULL, isB ? distB : distA, owner);      // exact dist
                int   pj1 = __shfl_sync(FULL, isB ? pB : pA, owner);     // owner row
                float uj1 = __shfl_sync(FULL, isB ? uB_c : uA_c, owner); // cached u[row]
                j0 = col + 1;
                if (pj1 == 0) break;
                ucur = uj1;
                Crow = &C[(pj1 - 1) * 64];
            }

            // deferred potential updates (registers only)
            const float distF = d0;
            if (usedA) { float a = distF - distA; vA -= a; uA_c += a; }
            if (usedB) { float a = distF - distB; vB -= a; uB_c += a; }
            const float ui_new = u_i_start + distF;   // final u of row i

            // augment along alternating path, moving u caches with ownership
            while (j0) {
                int o = (j0 - 1) & 31;
                int jprev = __shfl_sync(FULL, (j0 > 32) ? wayB : wayA, o);
                int jp = jprev > 0 ? jprev : 1;
                int osrc = (jp - 1) & 31;
                int   pprev = __shfl_sync(FULL, (jp > 32) ? pB : pA, osrc);
                float uprev = __shfl_sync(FULL, (jp > 32) ? uB_c : uA_c, osrc);
                if (jprev == 0) { pprev = i; uprev = ui_new; }
                if (lane == o) {
                    if (j0 > 32) { pB = pprev; uB_c = uprev; }
                    else         { pA = pprev; uA_c = uprev; }
                }
                j0 = jprev;
            }
        }

        // ---- matched L1 loss ----
        float coord = 0.f, width = 0.f;
        if (pA > 0) {
            int pr = transposed ? (jA - 1) : (pA - 1);
            int gr = transposed ? (pA - 1) : (jA - 1);
            const float* a = &ps[pr * 10];
            const float* g = &gt[gr * 10];
            #pragma unroll
            for (int k = 0; k < 8; k++) coord += fabsf(a[k] - g[k]);
            width += fabsf(a[8] - g[8]) + fabsf(a[9] - g[9]);
        }
        if (pB > 0) {
            int pr = transposed ? (jB - 1) : (pB - 1);
            int gr = transposed ? (pB - 1) : (jB - 1);
            const float* a = &ps[pr * 10];
            const float* g = &gt[gr * 10];
            #pragma unroll
            for (int k = 0; k < 8; k++) coord += fabsf(a[k] - g[k]);
            width += fabsf(a[8] - g[8]) + fabsf(a[9] - g[9]);
        }
        #pragma unroll
        for (int o = 16; o; o >>= 1) {
            coord += __shfl_xor_sync(FULL, coord, o);
            width += __shfl_xor_sync(FULL, width, o);
        }
        float ngf = (float)n;
        loss = 5.f * coord / (ngf * 8.f) + width / (ngf * 2.f) + bce_sh;
    }

    // ---- fused final reduction (last warp reduces in fixed order -> deterministic) ----
    if (lane == 0) g_loss[b] = loss;
    __threadfence();
    unsigned ticket = 0;
    if (lane == 0) ticket = atomicAdd(&g_count, 1u);
    ticket = __shfl_sync(FULL, ticket, 0);
    if (ticket == BATCH - 1) {
        __threadfence();
        float s = 0.f;
        #pragma unroll
        for (int k = 0; k < BATCH / 32; k++) s += __ldcg(&g_loss[lane + 32 * k]);
        #pragma unroll
        for (int o = 16; o; o >>= 1) s += __shfl_xor_sync(FULL, s, o);
        if (lane == 0) {
            out[0] = s * (1.f / (float)BATCH);
            g_count = 0;
        }
    }
}

extern "C" void kernel_launch(void* const* d_in, const int* in_sizes, int n_in,
                              void* d_out, int out_size) {
    const float* pred_strokes  = (const float*)d_in[0];
    const float* pred_validity = (const float*)d_in[1];
    const float* targets       = (const float*)d_in[2];
    float* out = (float*)d_out;

    detr_fused_kernel<<<BATCH, 128>>>(pred_strokes, pred_validity, targets, out);
}

// round 16
// speedup vs baseline: 1.1387x; 1.1387x over previous
#include <cuda_runtime.h>
#include <math.h>

#define BATCH 256
#define S 64

__device__ float g_loss[BATCH];
__device__ unsigned int g_count;

// order-preserving float<->uint keys
__device__ __forceinline__ unsigned okey(float f) {
    unsigned u = __float_as_uint(f);
    return u ^ (((unsigned)((int)u >> 31)) | 0x80000000u);
}
__device__ __forceinline__ float dokey(unsigned k) {
    unsigned m = (((unsigned)((int)(~k) >> 31)) | 0x80000000u);
    return __uint_as_float(k ^ m);
}

// numpy pairwise-order cost, no FMA contraction
__device__ __forceinline__ float cost10(const float* a, const float* g) {
    float d0 = fabsf(a[0] - g[0]), d1 = fabsf(a[1] - g[1]);
    float d2 = fabsf(a[2] - g[2]), d3 = fabsf(a[3] - g[3]);
    float d4 = fabsf(a[4] - g[4]), d5 = fabsf(a[5] - g[5]);
    float d6 = fabsf(a[6] - g[6]), d7 = fabsf(a[7] - g[7]);
    float d8 = fabsf(a[8] - g[8]), d9 = fabsf(a[9] - g[9]);
    float s8 = __fadd_rn(__fadd_rn(__fadd_rn(d0, d1), __fadd_rn(d2, d3)),
                         __fadd_rn(__fadd_rn(d4, d5), __fadd_rn(d6, d7)));
    return __fadd_rn(__fmul_rn(5.f, s8), __fadd_rn(d8, d9));
}

__global__ void __launch_bounds__(128) detr_fused_kernel(
    const float* __restrict__ pred_strokes,   // [B,S,10]
    const float* __restrict__ pred_validity,  // [B,S,1]
    const float* __restrict__ targets,        // [B,S,11]
    float* __restrict__ out)
{
    const int b = blockIdx.x;
    const int tid = threadIdx.x;
    const int wid = tid >> 5;
    const int lane = tid & 31;
    const unsigned FULL = 0xffffffffu;
    const float INFV = __int_as_float(0x7f800000);

    __shared__ float ps[S * 10];
    __shared__ float gt[S * 10];
    __shared__ float C[S * 64];
    __shared__ float u_sh[S + 1];              // read-only after build
    __shared__ unsigned long long tight[S];
    __shared__ int   validIdx[S];
    __shared__ float bce_sh;
    __shared__ int   n_sh;

    const float* tgb = targets + b * (S * 11);
    const float* psb = pred_strokes + b * (S * 10);
    const float* pvb = pred_validity + b * S;

    // ---- stage 1: ps staging (all warps), compaction (warp0), BCE (warp1) ----
    for (int idx = tid; idx < S * 10; idx += 128) ps[idx] = psb[idx];

    if (wid == 0) {
        float gv0 = tgb[lane * 11 + 10];
        float gv1 = tgb[(lane + 32) * 11 + 10];
        unsigned m0 = __ballot_sync(FULL, gv0 > 0.5f);
        unsigned m1 = __ballot_sync(FULL, gv1 > 0.5f);
        int c0 = __popc(m0);
        int nn = c0 + __popc(m1);
        unsigned lt = (1u << lane) - 1u;
        if (gv0 > 0.5f) validIdx[__popc(m0 & lt)] = lane;
        if (gv1 > 0.5f) validIdx[c0 + __popc(m1 & lt)] = lane + 32;
        if (lane == 0) n_sh = nn;
    } else if (wid == 1) {
        float gv0 = tgb[lane * 11 + 10];
        float gv1 = tgb[(lane + 32) * 11 + 10];
        float pv0 = pvb[lane], pv1 = pvb[lane + 32];
        float bce = -(gv0 * fmaxf(logf(pv0), -100.f) + (1.f - gv0) * fmaxf(logf(1.f - pv0), -100.f))
                    - (gv1 * fmaxf(logf(pv1), -100.f) + (1.f - gv1) * fmaxf(logf(1.f - pv1), -100.f));
        #pragma unroll
        for (int o = 16; o; o >>= 1) bce += __shfl_xor_sync(FULL, bce, o);
        if (lane == 0) bce_sh = bce * (1.f / 64.f);
    }
    __syncthreads();

    const int n = n_sh;
    const bool transposed = (n < 64);

    // ---- stage 2: gt staging, each warp stages its own build row range ----
    const int r0 = (wid * n) >> 2;
    const int r1 = ((wid + 1) * n) >> 2;
    for (int idx = r0 * 10 + lane; idx < r1 * 10; idx += 32) {
        int r = idx / 10, k = idx - r * 10;
        gt[idx] = tgb[validIdx[r] * 11 + k];
    }
    __syncthreads();

    // ---- stage 3: cost build (4-way row split) + per-row raw min + tight mask ----
    if (n > 0) {
        if (transposed) {
            float pa[10], pb[10];
            #pragma unroll
            for (int k = 0; k < 10; k++) {
                pa[k] = ps[lane * 10 + k];
                pb[k] = ps[(lane + 32) * 10 + k];
            }
            for (int i = r0; i < r1; i++) {
                float g[10];
                #pragma unroll
                for (int k = 0; k < 10; k++) g[k] = gt[i * 10 + k];  // broadcast
                float cA = cost10(pa, g);
                float cB = cost10(pb, g);
                C[i * 64 + lane] = cA;
                C[i * 64 + lane + 32] = cB;
                unsigned mk = __reduce_min_sync(FULL, min(okey(cA), okey(cB)));
                float ui = dokey(mk);
                unsigned bA = __ballot_sync(FULL, cA == ui);
                unsigned bB = __ballot_sync(FULL, cB == ui);
                if (lane == 0) {
                    u_sh[i + 1] = ui;
                    tight[i] = (unsigned long long)bA | ((unsigned long long)bB << 32);
                }
            }
        } else {
            // generic n==64 path (statistically never taken): build split by tid
            for (int idx = tid; idx < 64 * 64; idx += 128) {
                int i = idx >> 6, j = idx & 63;
                C[idx] = cost10(&ps[i * 10], &gt[j * 10]);
            }
        }
    }
    __syncthreads();

    if (wid != 0) return;   // warps 1-3 done; warp 0 owns the sequential tail

    float loss;
    if (n == 0) {
        loss = bce_sh;
    } else {
        if (!transposed) {
            // generic path: row mins + tight masks (warp 0, per-row cooperative)
            for (int i = 0; i < n; i++) {
                float cA = C[i * 64 + lane];
                float cB = C[i * 64 + lane + 32];
                unsigned mk = __reduce_min_sync(FULL, min(okey(cA), okey(cB)));
                float ui = dokey(mk);
                unsigned bA = __ballot_sync(FULL, cA == ui);
                unsigned bB = __ballot_sync(FULL, cB == ui);
                if (lane == 0) {
                    u_sh[i + 1] = ui;
                    tight[i] = (unsigned long long)bA | ((unsigned long long)bB << 32);
                }
            }
            __syncwarp();
        }

        const int jA = lane + 1, jB = lane + 33;
        float vA = 0.f, vB = 0.f;
        int pA = 0, pB = 0;
        unsigned long long rowdone = 0ull;

        // ---- greedy tight-edge assignment (scalar bitmask scan, prefetched) ----
        {
            unsigned long long freecols = ~0ull;
            unsigned long long tcur = tight[0];
            for (int i = 0; i < n; i++) {
                int nxt = (i + 1 < S) ? (i + 1) : (S - 1);
                unsigned long long tnext = tight[nxt];   // prefetch next row's mask
                unsigned long long t = tcur & freecols;
                if (t) {
                    int j = __ffsll((long long)t) - 1;   // column index 0..63
                    freecols &= ~(1ull << j);
                    rowdone |= 1ull << i;
                    if (j == lane) pA = i + 1;
                    if (j == lane + 32) pB = i + 1;
                }
                tcur = tnext;
            }
        }

        // dual cache: owning lane of each assigned column caches u[p[col]]
        float uA_c = (pA > 0) ? u_sh[pA] : 0.f;
        float uB_c = (pB > 0) ? u_sh[pB] : 0.f;

        // ---- shortest augmenting path phases for remaining rows ----
        // u_sh read-only; dual updates in registers; no shared writes, no syncwarp.
        for (int i = 1; i <= n; i++) {
            if ((rowdone >> (i - 1)) & 1ull) continue;

            float distA = INFV, distB = INFV;
            int wayA = 0, wayB = 0;
            bool usedA = false, usedB = false;
            const float u_i_start = u_sh[i];   // build value: free rows never updated
            float ucur = u_i_start;
            float d0 = 0.f;
            int j0 = 0;
            const float* Crow = &C[(i - 1) * 64];

            while (true) {
                if (j0 == jA) usedA = true;
                if (j0 == jB) usedB = true;

                float base = d0 - ucur;
                if (!usedA) {
                    float cur = base + (Crow[lane] - vA);
                    if (cur < distA) { distA = cur; wayA = j0; }
                }
                if (!usedB) {
                    float cur = base + (Crow[lane + 32] - vB);
                    if (cur < distB) { distB = cur; wayB = j0; }
                }
                // packed argmin: key's 6 LSBs carry the column index
                unsigned kA = usedA ? 0xFFFFFFFFu : okey(distA);
                unsigned kB = usedB ? 0xFFFFFFFFu : okey(distB);
                unsigned pkA = (kA & 0xFFFFFFC0u) | (unsigned)lane;
                unsigned pkB = (kB & 0xFFFFFFC0u) | (unsigned)(lane + 32);
                unsigned w = __reduce_min_sync(FULL, min(pkA, pkB));
                int col = (int)(w & 63u);
                int owner = col & 31;
                bool isB = col >= 32;
                d0 = __shfl_sync(FULL, isB ? distB : distA, owner);      // exact dist
                int   pj1 = __shfl_sync(FULL, isB ? pB : pA, owner);     // owner row
                float uj1 = __shfl_sync(FULL, isB ? uB_c : uA_c, owner); // cached u[row]
                j0 = col + 1;
                if (pj1 == 0) break;
                ucur = uj1;
                Crow = &C[(pj1 - 1) * 64];
            }

            // deferred potential updates (registers only)
            const float distF = d0;
            if (usedA) { float a = distF - distA; vA -= a; uA_c += a; }
            if (usedB) { float a = distF - distB; vB -= a; uB_c += a; }
            const float ui_new = u_i_start + distF;   // final u of row i

            // augment along alternating path, moving u caches with ownership
            while (j0) {
                int o = (j0 - 1) & 31;
                int jprev = __shfl_sync(FULL, (j0 > 32) ? wayB : wayA, o);
                int jp = jprev > 0 ? jprev : 1;
                int osrc = (jp - 1) & 31;
                int   pprev = __shfl_sync(FULL, (jp > 32) ? pB : pA, osrc);
                float uprev = __shfl_sync(FULL, (jp > 32) ? uB_c : uA_c, osrc);
                if (jprev == 0) { pprev = i; uprev = ui_new; }
                if (lane == o) {
                    if (j0 > 32) { pB = pprev; uB_c = uprev; }
                    else         { pA = pprev; uA_c = uprev; }
                }
                j0 = jprev;
            }
        }

        // ---- matched L1 loss ----
        float coord = 0.f, width = 0.f;
        if (pA > 0) {
            int pr = transposed ? (jA - 1) : (pA - 1);
            int gr = transposed ? (pA - 1) : (jA - 1);
            const float* a = &ps[pr * 10];
            const float* g = &gt[gr * 10];
            #pragma unroll
            for (int k = 0; k < 8; k++) coord += fabsf(a[k] - g[k]);
            width += fabsf(a[8] - g[8]) + fabsf(a[9] - g[9]);
        }
        if (pB > 0) {
            int pr = transposed ? (jB - 1) : (pB - 1);
            int gr = transposed ? (pB - 1) : (jB - 1);
            const float* a = &ps[pr * 10];
            const float* g = &gt[gr * 10];
            #pragma unroll
            for (int k = 0; k < 8; k++) coord += fabsf(a[k] - g[k]);
            width += fabsf(a[8] - g[8]) + fabsf(a[9] - g[9]);
        }
        #pragma unroll
        for (int o = 16; o; o >>= 1) {
            coord += __shfl_xor_sync(FULL, coord, o);
            width += __shfl_xor_sync(FULL, width, o);
        }
        float ngf = (float)n;
        loss = 5.f * coord / (ngf * 8.f) + width / (ngf * 2.f) + bce_sh;
    }

    // ---- fused final reduction (last warp reduces in fixed order -> deterministic) ----
    if (lane == 0) g_loss[b] = loss;
    __threadfence();
    unsigned ticket = 0;
    if (lane == 0) ticket = atomicAdd(&g_count, 1u);
    ticket = __shfl_sync(FULL, ticket, 0);
    if (ticket == BATCH - 1) {
        __threadfence();
        float s = 0.f;
        #pragma unroll
        for (int k = 0; k < BATCH / 32; k++) s += __ldcg(&g_loss[lane + 32 * k]);
        #pragma unroll
        for (int o = 16; o; o >>= 1) s += __shfl_xor_sync(FULL, s, o);
        if (lane == 0) {
            out[0] = s * (1.f / (float)BATCH);
            g_count = 0;
        }
    }
}

extern "C" void kernel_launch(void* const* d_in, const int* in_sizes, int n_in,
                              void* d_out, int out_size) {
    const float* pred_strokes  = (const float*)d_in[0];
    const float* pred_validity = (const float*)d_in[1];
    const float* targets       = (const float*)d_in[2];
    float* out = (float*)d_out;

    detr_fused_kernel<<<BATCH, 128>>>(pred_strokes, pred_validity, targets, out);
}